// round 8
// baseline (speedup 1.0000x reference)
#include <cuda_runtime.h>
#include <cuda_bf16.h>
#include <math.h>

// ---------------- problem constants ----------------
#define BB     4
#define NN     1280
#define NM     256
#define NS     1024
#define CC     768
#define HH     12
#define DD     64
#define MEM    1280
#define KFULL  (MEM + NN)     // 2560
#define TOPM   128            // int(0.5*256)
#define TOPS   640            // int(0.25*2560)
#define SCALE  0.125f         // 1/R, R=8
#define QSC    0.125f         // D^-0.5 = 64^-0.5
#define KST    68             // K/V smem row stride (floats): 16B-aligned, conflict-benign
#define QT     16             // attn_s queries per block
#define NT     512            // attn_s threads per block

// ---------------- device scratch (no allocs allowed) ----------------
__device__ float g_WtQKV[CC * 3 * CC];     // (K=768, N=2304) transposed effective W_qkv
__device__ float g_WtIDV[CC * CC];         // (768, 768)
__device__ float g_WtPROJ[CC * CC];        // (768, 768)  plain transpose of W_proj
__device__ float g_WIDK[HH * CC];          // (12, 768)   effective W_idk (row-major)
__device__ float g_QKV[BB * NN * 3 * CC];  // (5120, 2304)
__device__ float g_IDK[BB * NM * HH];      // (1024, 12)
__device__ float g_IDV[BB * NM * CC];      // (1024, 768)
__device__ float g_XO[BB * NN * CC];       // (5120, 768)

// ---------------- helpers ----------------
__device__ __forceinline__ unsigned f2u(float f) {
    unsigned u = __float_as_uint(f);
    return (u & 0x80000000u) ? ~u : (u | 0x80000000u);
}

// warp-aggregated histogram add: lanes with same bin elect a leader that adds popc.
// bin == 0xFFFFFFFF means "no contribution". All 32 lanes must participate.
__device__ __forceinline__ void hist_add_warp(unsigned* hist, unsigned bin) {
    unsigned peers = __match_any_sync(0xffffffffu, bin);
    if (bin != 0xffffffffu) {
        int lane = threadIdx.x & 31;
        int leader = __ffs(peers) - 1;
        if (lane == leader) atomicAdd(&hist[bin], (unsigned)__popc(peers));
    }
}

// block reductions: warp shuffle + one cross-warp stage; result broadcast to all.
// red needs >= NTHREADS/32 floats. Ends with the block synchronized.
template<int NTHREADS>
__device__ __forceinline__ float block_reduce_max(float v, float* red, int tid) {
    #pragma unroll
    for (int o = 16; o > 0; o >>= 1) v = fmaxf(v, __shfl_xor_sync(0xffffffffu, v, o));
    if ((tid & 31) == 0) red[tid >> 5] = v;
    __syncthreads();
    if (tid < 32) {
        float w = (tid < NTHREADS / 32) ? red[tid] : -3.4e38f;
        #pragma unroll
        for (int o = 16; o > 0; o >>= 1) w = fmaxf(w, __shfl_xor_sync(0xffffffffu, w, o));
        if (tid == 0) red[0] = w;
    }
    __syncthreads();
    float r = red[0];
    __syncthreads();
    return r;
}

template<int NTHREADS>
__device__ __forceinline__ float block_reduce_sum(float v, float* red, int tid) {
    #pragma unroll
    for (int o = 16; o > 0; o >>= 1) v += __shfl_xor_sync(0xffffffffu, v, o);
    if ((tid & 31) == 0) red[tid >> 5] = v;
    __syncthreads();
    if (tid < 32) {
        float w = (tid < NTHREADS / 32) ? red[tid] : 0.f;
        #pragma unroll
        for (int o = 16; o > 0; o >>= 1) w += __shfl_xor_sync(0xffffffffu, w, o);
        if (tid == 0) red[0] = w;
    }
    __syncthreads();
    float r = red[0];
    __syncthreads();
    return r;
}

// warp-parallel descending histogram select: finds highest bin where cumulative
// count (from bin 255 downward) reaches *rem. Executed by threads tid<32.
// Updates s_pfx / s_remain. Caller must __syncthreads() after.
__device__ __forceinline__ void hist_select_warp(const unsigned* hist, int tid,
                                                 unsigned pfx, int shift,
                                                 volatile unsigned* s_pfx,
                                                 volatile int* s_remain) {
    if (tid < 32) {
        int base = tid * 8;
        int hv[8], chunk = 0;
        #pragma unroll
        for (int r = 0; r < 8; r++) { hv[r] = (int)hist[base + r]; chunk += hv[r]; }
        // inclusive suffix sum across lanes (lane l gets sum over lanes >= l)
        int suf = chunk;
        #pragma unroll
        for (int o = 1; o < 32; o <<= 1) {
            int t = __shfl_down_sync(0xffffffffu, suf, o);
            if (tid + o < 32) suf += t;
        }
        int above = suf - chunk;      // count in strictly higher chunks
        int rem = *s_remain;
        __syncwarp();
        if (above < rem && suf >= rem) {   // exactly one lane
            int c = above;
            #pragma unroll
            for (int r2 = 7; r2 >= 0; r2--) {
                int nc = c + hv[r2];
                if (nc >= rem) {
                    *s_remain = rem - c;
                    *s_pfx = pfx | ((unsigned)(base + r2) << shift);
                    break;
                }
                c = nc;
            }
        }
    }
}

// ---------------- prep kernels: fold LoRA into weights, transpose ----------------
__global__ void prep_qkv_eff(const float* __restrict__ W, const float* __restrict__ A,
                             const float* __restrict__ Bm) {
    int idx = blockIdx.x * 256 + threadIdx.x;
    if (idx >= CC * 3 * CC) return;
    int o = idx % (3 * CC), c = idx / (3 * CC);
    int g = o / CC, oc = o % CC;
    float s = 0.f;
    #pragma unroll
    for (int r = 0; r < 8; r++)
        s += Bm[(g * CC + oc) * 8 + r] * A[(g * 8 + r) * CC + c];
    g_WtQKV[c * (3 * CC) + o] = W[o * CC + c] + SCALE * s;
}

__global__ void prep_idv_eff(const float* __restrict__ W, const float* __restrict__ A,
                             const float* __restrict__ Bm) {
    int idx = blockIdx.x * 256 + threadIdx.x;
    if (idx >= CC * CC) return;
    int o = idx % CC, c = idx / CC;
    float s = 0.f;
    #pragma unroll
    for (int r = 0; r < 8; r++)
        s += Bm[o * 8 + r] * A[r * CC + c];
    g_WtIDV[c * CC + o] = W[o * CC + c] + SCALE * s;
}

__global__ void prep_proj_t(const float* __restrict__ W) {
    int idx = blockIdx.x * 256 + threadIdx.x;
    if (idx >= CC * CC) return;
    int o = idx % CC, c = idx / CC;
    g_WtPROJ[c * CC + o] = W[o * CC + c];
}

__global__ void prep_idk_eff(const float* __restrict__ W, const float* __restrict__ A,
                             const float* __restrict__ Bm) {
    int idx = blockIdx.x * 256 + threadIdx.x;
    if (idx >= HH * CC) return;
    int h = idx / CC, c = idx % CC;
    float s = 0.f;
    #pragma unroll
    for (int r = 0; r < 8; r++)
        s += Bm[h * 8 + r] * A[r * CC + c];
    g_WIDK[idx] = W[idx] + SCALE * s;
}

// ---------------- generic SGEMM: C(M,N) = A(M,K) @ Bt(K,N) + bias ----------------
// 128x128 tile, BK=8, 256 threads, 8x8 per thread, float4 smem reads,
// register-prefetch software pipeline on the global loads.
__global__ void __launch_bounds__(256) sgemm128(const float* __restrict__ A,
                                                const float* __restrict__ Bt,
                                                const float* __restrict__ bias,
                                                float* __restrict__ C,
                                                int M, int N, int K) {
    __shared__ float As[8][128];
    __shared__ float Bs[8][128];
    int tid = threadIdx.x;
    int bx = blockIdx.x * 128;   // N
    int by = blockIdx.y * 128;   // M
    int tR = tid / 16, tC = tid % 16;
    float acc[8][8];
    #pragma unroll
    for (int i = 0; i < 8; i++)
        #pragma unroll
        for (int j = 0; j < 8; j++) acc[i][j] = 0.f;

    int aRow = tid / 2, aCol = (tid % 2) * 4;
    int bRow = tid / 32, bCol = (tid % 32) * 4;
    const float* Aptr = A + (long)(by + aRow) * K + aCol;
    const float* Bptr = Bt + (long)bRow * N + bx + bCol;

    // prologue load
    float4 a4 = *(const float4*)(Aptr);
    float4 b4 = *(const float4*)(Bptr);

    for (int k0 = 0; k0 < K; k0 += 8) {
        // commit current tile to smem
        As[aCol + 0][aRow] = a4.x;
        As[aCol + 1][aRow] = a4.y;
        As[aCol + 2][aRow] = a4.z;
        As[aCol + 3][aRow] = a4.w;
        *(float4*)&Bs[bRow][bCol] = b4;
        __syncthreads();
        // prefetch next tile into registers (latency overlapped with compute)
        if (k0 + 8 < K) {
            a4 = *(const float4*)(Aptr + k0 + 8);
            b4 = *(const float4*)(Bptr + (long)(k0 + 8) * N);
        }
        #pragma unroll
        for (int k = 0; k < 8; k++) {
            float4 ra0 = *(const float4*)&As[k][tR * 8];
            float4 ra1 = *(const float4*)&As[k][tR * 8 + 4];
            float4 rb0 = *(const float4*)&Bs[k][tC * 8];
            float4 rb1 = *(const float4*)&Bs[k][tC * 8 + 4];
            float ra[8] = {ra0.x, ra0.y, ra0.z, ra0.w, ra1.x, ra1.y, ra1.z, ra1.w};
            float rb[8] = {rb0.x, rb0.y, rb0.z, rb0.w, rb1.x, rb1.y, rb1.z, rb1.w};
            #pragma unroll
            for (int i = 0; i < 8; i++)
                #pragma unroll
                for (int j = 0; j < 8; j++) acc[i][j] += ra[i] * rb[j];
        }
        __syncthreads();
    }
    #pragma unroll
    for (int i = 0; i < 8; i++) {
        int row = by + tR * 8 + i;
        #pragma unroll
        for (int j = 0; j < 8; j += 4) {
            int col = bx + tC * 8 + j;
            float4 o;
            o.x = acc[i][j + 0] + bias[col + 0];
            o.y = acc[i][j + 1] + bias[col + 1];
            o.z = acc[i][j + 2] + bias[col + 2];
            o.w = acc[i][j + 3] + bias[col + 3];
            *(float4*)(C + (long)row * N + col) = o;
        }
    }
}

// ---------------- ID_K: (1024 tokens, 12 heads) ----------------
__global__ void idk_kernel(const float* __restrict__ id_total, const float* __restrict__ b_idk) {
    int token = blockIdx.x;                 // 0..1023 (= b*256+n)
    int w = threadIdx.x >> 5, lane = threadIdx.x & 31;  // 12 warps
    const float* row = id_total + (long)token * CC;
    const float* wr = g_WIDK + w * CC;
    float s = 0.f;
    for (int c = lane; c < CC; c += 32) s += row[c] * wr[c];
    #pragma unroll
    for (int o = 16; o > 0; o >>= 1) s += __shfl_down_sync(0xffffffffu, s, o);
    if (lane == 0) g_IDK[token * HH + w] = s + b_idk[w];
}

// ---------------- k_m_id / v_m_id (also the 2nd & 3rd outputs) ----------------
__global__ void kvmid_kernel(float* __restrict__ kmid, float* __restrict__ vmid) {
    int idx = blockIdx.x * 256 + threadIdx.x;
    if (idx >= BB * HH * NM * DD) return;
    int d = idx & 63;
    int t = idx >> 6;
    int n = t & 255; t >>= 8;
    int h = t % HH;  int b = t / HH;
    const float* q = g_QKV + (long)(b * NN + n) * (3 * CC);
    float idk = g_IDK[(b * NM + n) * HH + h];
    kmid[idx] = q[CC + h * DD + d] * (1.0f + tanhf(idk));
    vmid[idx] = q[2 * CC + h * DD + d] + g_IDV[(long)(b * NM + n) * CC + h * DD + d];
}

// ---------------- fused attn over memory tokens (256 keys, top-128) ----------------
// grid (NM/8, H, B), 256 threads
__global__ void __launch_bounds__(256) attn_m_kernel(const float* __restrict__ kmid,
                                                     const float* __restrict__ vmid) {
    extern __shared__ float sm[];
    float* Qs = sm;                 // 512
    float* Ks = Qs + 512;           // 256*KST
    float* Vs = Ks + 256 * KST;     // 256*KST
    float* Sc = Vs + 256 * KST;     // 8*256
    float* red = Sc + 8 * 256;      // 256
    unsigned* hist = (unsigned*)(red + 256); // 256
    __shared__ unsigned s_pfx;
    __shared__ int s_remain;

    int tid = threadIdx.x;
    int q0 = blockIdx.x * 8, h = blockIdx.y, b = blockIdx.z;
    int bh = b * HH + h;

    for (int i = tid; i < 8 * DD; i += 256) {
        int qq = i >> 6, d = i & 63;
        Qs[i] = g_QKV[(long)(b * NN + q0 + qq) * (3 * CC) + h * DD + d] * QSC;
    }
    for (int i = tid; i < NM * DD; i += 256) {
        int kk = i >> 6, d = i & 63;
        Ks[kk * KST + d] = kmid[((long)bh * NM + kk) * DD + d];
        Vs[kk * KST + d] = vmid[((long)bh * NM + kk) * DD + d];
    }
    __syncthreads();

    {
        const float4* K4 = (const float4*)&Ks[tid * KST];
        for (int qq = 0; qq < 8; qq++) {
            const float4* Q4 = (const float4*)&Qs[qq * DD];
            float s = 0.f;
            #pragma unroll
            for (int d4 = 0; d4 < DD / 4; d4++) {
                float4 kv = K4[d4], qv = Q4[d4];
                s += qv.x * kv.x + qv.y * kv.y + qv.z * kv.z + qv.w * kv.w;
            }
            Sc[qq * 256 + tid] = s;
        }
    }
    __syncthreads();

    for (int qq = 0; qq < 8; qq++) {
        float* row = Sc + qq * 256;
        float myv = row[tid];
        float mx = block_reduce_max<256>(myv, red, tid);
        // radix select top-128 threshold
        if (tid == 0) { s_pfx = 0u; s_remain = TOPM; }
        __syncthreads();
        for (int pass = 0; pass < 4; pass++) {
            int shift = 24 - pass * 8;
            hist[tid] = 0u;
            __syncthreads();
            unsigned pmask = (pass == 0) ? 0u : (0xFFFFFFFFu << (shift + 8));
            unsigned pfx = s_pfx;
            unsigned u = f2u(myv);
            unsigned bin = ((u & pmask) == pfx) ? ((u >> shift) & 255u) : 0xffffffffu;
            hist_add_warp(hist, bin);
            __syncthreads();
            hist_select_warp(hist, tid, pfx, shift, &s_pfx, &s_remain);
            __syncthreads();
        }
        unsigned thr = s_pfx;
        float w = (f2u(myv) >= thr) ? __expf(myv - mx) : 0.f;
        row[tid] = w;
        float sum = block_reduce_sum<256>(w, red, tid);
        float inv = 1.0f / sum;
        // AV
        int g = tid >> 6, d = tid & 63;
        float acc = 0.f;
        for (int i = g; i < NM; i += 4) acc += row[i] * Vs[i * KST + d];
        red[tid] = acc; __syncthreads();
        if (tid < 64) {
            float o = (red[tid] + red[tid + 64] + red[tid + 128] + red[tid + 192]) * inv;
            g_XO[(long)(b * NN + q0 + qq) * CC + h * DD + tid] = o;
        }
        __syncthreads();
    }
}

// ---------------- fused attn over full keys (2560 keys, top-640) ----------------
// grid (NS/QT, H, B), NT=512 threads, QT=16 queries per block
__global__ void __launch_bounds__(NT) attn_s_kernel(const float* __restrict__ mem_k,
                                                    const float* __restrict__ mem_v,
                                                    const float* __restrict__ vmid) {
    extern __shared__ float sm[];
    float* Qs = sm;                   // QT*64 = 1024
    float* Ks = Qs + QT * DD;         // 64*KST = 4352
    float* Sc = Ks + 64 * KST;        // QT*2560 = 40960
    float* red = Sc + QT * KFULL;     // NT = 512
    float* selw = red + NT;           // 704
    int*   selidx = (int*)(selw + 704);       // 704
    unsigned* hist = (unsigned*)(selidx + 704); // 256
    __shared__ unsigned s_pfx;
    __shared__ int s_remain;
    __shared__ int s_cnt;

    int tid = threadIdx.x;
    int q0 = blockIdx.x * QT, h = blockIdx.y, b = blockIdx.z;
    int bh = b * HH + h;

    for (int i = tid; i < QT * DD; i += NT) {
        int qq = i >> 6, d = i & 63;
        Qs[i] = g_QKV[(long)(b * NN + NM + q0 + qq) * (3 * CC) + h * DD + d] * QSC;
    }
    __syncthreads();

    // scores in 64-key chunks
    for (int c0 = 0; c0 < KFULL; c0 += 64) {
        for (int i = tid; i < 64 * DD; i += NT) {
            int kl = i >> 6, d = i & 63;
            int kg = c0 + kl;
            float v;
            if (kg < MEM)
                v = mem_k[((long)bh * MEM + kg) * DD + d];
            else
                v = g_QKV[(long)(b * NN + (kg - MEM)) * (3 * CC) + CC + h * DD + d];
            Ks[kl * KST + d] = v;
        }
        __syncthreads();
        int kl = tid & 63, qp = tid >> 6;   // 8 q-groups
        const float4* K4 = (const float4*)&Ks[kl * KST];
        #pragma unroll
        for (int qi = 0; qi < QT / 8; qi++) {
            int qq = qp + qi * 8;
            const float4* Q4 = (const float4*)&Qs[qq * DD];
            float s = 0.f;
            #pragma unroll
            for (int d4 = 0; d4 < DD / 4; d4++) {
                float4 kv = K4[d4], qv = Q4[d4];
                s += qv.x * kv.x + qv.y * kv.y + qv.z * kv.z + qv.w * kv.w;
            }
            Sc[qq * KFULL + c0 + kl] = s;
        }
        __syncthreads();
    }

    for (int qq = 0; qq < QT; qq++) {
        float* row = Sc + qq * KFULL;
        // row max
        float mv = -1e30f;
        for (int i = tid; i < KFULL; i += NT) mv = fmaxf(mv, row[i]);
        float mx = block_reduce_max<NT>(mv, red, tid);
        // radix select top-640 threshold
        if (tid == 0) { s_pfx = 0u; s_remain = TOPS; s_cnt = 0; }
        __syncthreads();
        for (int pass = 0; pass < 4; pass++) {
            int shift = 24 - pass * 8;
            if (tid < 256) hist[tid] = 0u;
            __syncthreads();
            unsigned pmask = (pass == 0) ? 0u : (0xFFFFFFFFu << (shift + 8));
            unsigned pfx = s_pfx;
            for (int i = tid; i < KFULL; i += NT) {
                unsigned u = f2u(row[i]);
                unsigned bin = ((u & pmask) == pfx) ? ((u >> shift) & 255u) : 0xffffffffu;
                hist_add_warp(hist, bin);
            }
            __syncthreads();
            hist_select_warp(hist, tid, pfx, shift, &s_pfx, &s_remain);
            __syncthreads();
        }
        unsigned thr = s_pfx;
        // compact selected + weight sum (warp-aggregated s_cnt)
        float lsum = 0.f;
        int lane = tid & 31;
        for (int i = tid; i < KFULL; i += NT) {
            float v = row[i];
            bool sel = (f2u(v) >= thr);
            unsigned ballot = __ballot_sync(0xffffffffu, sel);
            int base = 0;
            if (ballot) {
                int leader = __ffs(ballot) - 1;
                if (lane == leader) base = atomicAdd(&s_cnt, __popc(ballot));
                base = __shfl_sync(0xffffffffu, base, leader);
            }
            if (sel) {
                float w = __expf(v - mx);
                int p = base + __popc(ballot & ((1u << lane) - 1u));
                if (p < 704) { selidx[p] = i; selw[p] = w; }
                lsum += w;
            }
        }
        float sum = block_reduce_sum<NT>(lsum, red, tid);
        float inv = 1.0f / sum;
        int cnt = min(s_cnt, 704);
        __syncthreads();
        // AV over compacted selection (8-way key parallelism)
        int g = tid >> 6, d = tid & 63;
        float acc = 0.f;
        for (int j = g; j < cnt; j += 8) {
            int idx = selidx[j];
            const float* vrow;
            if (idx < MEM)
                vrow = mem_v + ((long)bh * MEM + idx) * DD;
            else if (idx < MEM + NM)
                vrow = vmid + ((long)bh * NM + (idx - MEM)) * DD;
            else
                vrow = g_QKV + (long)(b * NN + (idx - MEM)) * (3 * CC) + 2 * CC + h * DD;
            acc += selw[j] * vrow[d];
        }
        red[tid] = acc; __syncthreads();
        if (tid < 64) {
            float o = 0.f;
            #pragma unroll
            for (int k2 = 0; k2 < 8; k2++) o += red[tid + k2 * 64];
            g_XO[(long)(b * NN + NM + q0 + qq) * CC + h * DD + tid] = o * inv;
        }
        __syncthreads();
    }
}

// ---------------- MoE routed LoRA add: out += scale * sum_e route_e * B_e @ (A_e @ xo) ----------------
__global__ void moe_kernel(const float* __restrict__ route_W, const float* __restrict__ proj_A,
                           const float* __restrict__ proj_B, float* __restrict__ out) {
    __shared__ float row[CC];
    __shared__ float dots[36];
    __shared__ float coef[32];
    int token = blockIdx.x, tid = threadIdx.x;
    for (int i = tid; i < CC; i += 256) row[i] = g_XO[(long)token * CC + i];
    __syncthreads();
    int w = tid >> 5, lane = tid & 31;
    for (int j = w; j < 36; j += 8) {
        const float* vec = (j < 4) ? (route_W + (long)j * CC) : (proj_A + (long)(j - 4) * CC);
        float s = 0.f;
        for (int c = lane; c < CC; c += 32) s += row[c] * vec[c];
        #pragma unroll
        for (int o = 16; o > 0; o >>= 1) s += __shfl_down_sync(0xffffffffu, s, o);
        if (lane == 0) dots[j] = s;
    }
    __syncthreads();
    if (tid == 0) {
        float m = fmaxf(fmaxf(dots[0], dots[1]), fmaxf(dots[2], dots[3]));
        float e0 = __expf(dots[0] - m), e1 = __expf(dots[1] - m);
        float e2 = __expf(dots[2] - m), e3 = __expf(dots[3] - m);
        float inv = 1.f / (e0 + e1 + e2 + e3);
        float p[4] = {e0 * inv, e1 * inv, e2 * inv, e3 * inv};
        for (int e = 0; e < 4; e++)
            for (int r = 0; r < 8; r++)
                coef[e * 8 + r] = p[e] * dots[4 + e * 8 + r] * SCALE;
    }
    __syncthreads();
    for (int c = tid; c < CC; c += 256) {
        float acc = 0.f;
        #pragma unroll
        for (int e = 0; e < 4; e++)
            #pragma unroll
            for (int r = 0; r < 8; r++)
                acc += coef[e * 8 + r] * proj_B[((long)e * CC + c) * 8 + r];
        out[(long)token * CC + c] += acc;
    }
}

// ---------------- host ----------------
extern "C" void kernel_launch(void* const* d_in, const int* in_sizes, int n_in,
                              void* d_out, int out_size) {
    const float* x        = (const float*)d_in[0];
    const float* id_total = (const float*)d_in[1];
    const float* mem_k    = (const float*)d_in[2];
    const float* mem_v    = (const float*)d_in[3];
    const float* W_qkv    = (const float*)d_in[4];
    const float* b_qkv    = (const float*)d_in[5];
    const float* qkv_A    = (const float*)d_in[6];
    const float* qkv_B    = (const float*)d_in[7];
    const float* W_proj   = (const float*)d_in[8];
    const float* b_proj   = (const float*)d_in[9];
    const float* route_W  = (const float*)d_in[10];
    const float* proj_A   = (const float*)d_in[11];
    const float* proj_B   = (const float*)d_in[12];
    const float* W_idk    = (const float*)d_in[13];
    const float* b_idk    = (const float*)d_in[14];
    const float* idk_A    = (const float*)d_in[15];
    const float* idk_B    = (const float*)d_in[16];
    const float* W_idv    = (const float*)d_in[17];
    const float* b_idv    = (const float*)d_in[18];
    const float* idv_A    = (const float*)d_in[19];
    const float* idv_B    = (const float*)d_in[20];

    float* out  = (float*)d_out;                      // (4,1280,768)
    float* kmid = out + (long)BB * NN * CC;           // (4,12,256,64)
    float* vmid = kmid + (long)BB * HH * NM * DD;     // (4,12,256,64)

    void *p_WtQKV, *p_WtIDV, *p_WtPROJ, *p_QKV, *p_IDV, *p_XO;
    cudaGetSymbolAddress(&p_WtQKV, g_WtQKV);
    cudaGetSymbolAddress(&p_WtIDV, g_WtIDV);
    cudaGetSymbolAddress(&p_WtPROJ, g_WtPROJ);
    cudaGetSymbolAddress(&p_QKV, g_QKV);
    cudaGetSymbolAddress(&p_IDV, g_IDV);
    cudaGetSymbolAddress(&p_XO, g_XO);

    // prep: fold LoRA, transpose weights
    prep_qkv_eff<<<(CC * 3 * CC + 255) / 256, 256>>>(W_qkv, qkv_A, qkv_B);
    prep_idv_eff<<<(CC * CC + 255) / 256, 256>>>(W_idv, idv_A, idv_B);
    prep_proj_t<<<(CC * CC + 255) / 256, 256>>>(W_proj);
    prep_idk_eff<<<(HH * CC + 255) / 256, 256>>>(W_idk, idk_A, idk_B);

    // QKV gemm: (5120,768) @ (768,2304)
    {
        dim3 grid(3 * CC / 128, BB * NN / 128);
        sgemm128<<<grid, 256>>>(x, (const float*)p_WtQKV, b_qkv, (float*)p_QKV,
                                BB * NN, 3 * CC, CC);
    }
    // ID_K
    idk_kernel<<<BB * NM, HH * 32>>>(id_total, b_idk);
    // ID_V gemm: (1024,768) @ (768,768)
    {
        dim3 grid(CC / 128, BB * NM / 128);
        sgemm128<<<grid, 256>>>(id_total, (const float*)p_WtIDV, b_idv, (float*)p_IDV,
                                BB * NM, CC, CC);
    }
    // k_m_id / v_m_id -> outputs 2 & 3
    kvmid_kernel<<<(BB * HH * NM * DD + 255) / 256, 256>>>(kmid, vmid);

    // attention over memory tokens
    {
        size_t smem = (size_t)(512 + 256 * KST + 256 * KST + 8 * 256 + 256 + 256) * 4;
        cudaFuncSetAttribute(attn_m_kernel, cudaFuncAttributeMaxDynamicSharedMemorySize, (int)smem);
        dim3 grid(NM / 8, HH, BB);
        attn_m_kernel<<<grid, 256, smem>>>(kmid, vmid);
    }
    // attention over full keys
    {
        size_t smem = (size_t)(QT * DD + 64 * KST + QT * KFULL + NT + 704 + 704 + 256) * 4;
        cudaFuncSetAttribute(attn_s_kernel, cudaFuncAttributeMaxDynamicSharedMemorySize, (int)smem);
        dim3 grid(NS / QT, HH, BB);
        attn_s_kernel<<<grid, NT, smem>>>(mem_k, mem_v, vmid);
    }
    // output projection gemm: (5120,768) @ (768,768) -> out
    {
        dim3 grid(CC / 128, BB * NN / 128);
        sgemm128<<<grid, 256>>>((const float*)p_XO, (const float*)p_WtPROJ, b_proj, out,
                                BB * NN, CC, CC);
    }
    // MoE routed LoRA add
    moe_kernel<<<BB * NN, 256>>>(route_W, proj_A, proj_B, out);

    (void)in_sizes; (void)n_in; (void)out_size;
}

// round 11
// speedup vs baseline: 1.5306x; 1.5306x over previous
#include <cuda_runtime.h>
#include <cuda_bf16.h>
#include <math.h>

// ---------------- problem constants ----------------
#define BB     4
#define NN     1280
#define NM     256
#define NS     1024
#define CC     768
#define HH     12
#define DD     64
#define MEM    1280
#define KFULL  (MEM + NN)     // 2560
#define TOPM   128            // int(0.5*256)
#define TOPS   640            // int(0.25*2560)
#define SCALE  0.125f         // 1/R, R=8
#define QSC    0.125f         // D^-0.5 = 64^-0.5
#define KST    68             // K/V smem row stride (floats): 16B-aligned, conflict-benign
#define QT     16             // attn_s queries per block
#define NT     512            // attn_s threads per block

// ---------------- device scratch (no allocs allowed) ----------------
__device__ float g_WtQKV[CC * 3 * CC];     // (K=768, N=2304) transposed effective W_qkv
__device__ float g_WtIDV[CC * CC];         // (768, 768)
__device__ float g_WtPROJ[CC * CC];        // (768, 768)  plain transpose of W_proj
__device__ float g_WIDK[HH * CC];          // (12, 768)   effective W_idk (row-major)
__device__ float g_QKV[BB * NN * 3 * CC];  // (5120, 2304)
__device__ float g_IDK[BB * NM * HH];      // (1024, 12)
__device__ float g_IDV[BB * NM * CC];      // (1024, 768)
__device__ float g_XO[BB * NN * CC];       // (5120, 768)

// ---------------- helpers ----------------
__device__ __forceinline__ unsigned f2u(float f) {
    unsigned u = __float_as_uint(f);
    return (u & 0x80000000u) ? ~u : (u | 0x80000000u);
}

// warp-aggregated histogram add: lanes with same bin elect a leader that adds popc.
// bin == 0xFFFFFFFF means "no contribution". All 32 lanes must participate.
__device__ __forceinline__ void hist_add_warp(unsigned* hist, unsigned bin) {
    unsigned peers = __match_any_sync(0xffffffffu, bin);
    if (bin != 0xffffffffu) {
        int lane = threadIdx.x & 31;
        int leader = __ffs(peers) - 1;
        if (lane == leader) atomicAdd(&hist[bin], (unsigned)__popc(peers));
    }
}

// block reductions: warp shuffle + one cross-warp stage; result broadcast to all.
// red needs >= NTHREADS/32 floats. Ends with the block synchronized.
template<int NTHREADS>
__device__ __forceinline__ float block_reduce_max(float v, float* red, int tid) {
    #pragma unroll
    for (int o = 16; o > 0; o >>= 1) v = fmaxf(v, __shfl_xor_sync(0xffffffffu, v, o));
    if ((tid & 31) == 0) red[tid >> 5] = v;
    __syncthreads();
    if (tid < 32) {
        float w = (tid < NTHREADS / 32) ? red[tid] : -3.4e38f;
        #pragma unroll
        for (int o = 16; o > 0; o >>= 1) w = fmaxf(w, __shfl_xor_sync(0xffffffffu, w, o));
        if (tid == 0) red[0] = w;
    }
    __syncthreads();
    float r = red[0];
    __syncthreads();
    return r;
}

template<int NTHREADS>
__device__ __forceinline__ float block_reduce_sum(float v, float* red, int tid) {
    #pragma unroll
    for (int o = 16; o > 0; o >>= 1) v += __shfl_xor_sync(0xffffffffu, v, o);
    if ((tid & 31) == 0) red[tid >> 5] = v;
    __syncthreads();
    if (tid < 32) {
        float w = (tid < NTHREADS / 32) ? red[tid] : 0.f;
        #pragma unroll
        for (int o = 16; o > 0; o >>= 1) w += __shfl_xor_sync(0xffffffffu, w, o);
        if (tid == 0) red[0] = w;
    }
    __syncthreads();
    float r = red[0];
    __syncthreads();
    return r;
}

// warp-parallel descending histogram select: finds highest bin where cumulative
// count (from bin 255 downward) reaches *rem. Executed by threads tid<32.
// Updates s_pfx / s_remain. Caller must __syncthreads() after.
__device__ __forceinline__ void hist_select_warp(const unsigned* hist, int tid,
                                                 unsigned pfx, int shift,
                                                 volatile unsigned* s_pfx,
                                                 volatile int* s_remain) {
    if (tid < 32) {
        int base = tid * 8;
        int hv[8], chunk = 0;
        #pragma unroll
        for (int r = 0; r < 8; r++) { hv[r] = (int)hist[base + r]; chunk += hv[r]; }
        // inclusive suffix sum across lanes (lane l gets sum over lanes >= l)
        int suf = chunk;
        #pragma unroll
        for (int o = 1; o < 32; o <<= 1) {
            int t = __shfl_down_sync(0xffffffffu, suf, o);
            if (tid + o < 32) suf += t;
        }
        int above = suf - chunk;      // count in strictly higher chunks
        int rem = *s_remain;
        __syncwarp();
        if (above < rem && suf >= rem) {   // exactly one lane
            int c = above;
            #pragma unroll
            for (int r2 = 7; r2 >= 0; r2--) {
                int nc = c + hv[r2];
                if (nc >= rem) {
                    *s_remain = rem - c;
                    *s_pfx = pfx | ((unsigned)(base + r2) << shift);
                    break;
                }
                c = nc;
            }
        }
    }
}

// ---------------- single prep kernel: fold LoRA into weights, transpose ----------------
// ranges: [0, QKV_N) qkv_eff, [QKV_N, +IDV_N) idv_eff, [.., +PROJ_N) proj_t, [.., +IDK_N) idk_eff
#define QKV_N  (CC * 3 * CC)
#define IDV_N  (CC * CC)
#define PROJ_N (CC * CC)
#define IDK_N  (HH * CC)
#define PREP_TOTAL (QKV_N + IDV_N + PROJ_N + IDK_N)

__global__ void prep_all(const float* __restrict__ W_qkv, const float* __restrict__ qkv_A,
                         const float* __restrict__ qkv_B,
                         const float* __restrict__ W_idv, const float* __restrict__ idv_A,
                         const float* __restrict__ idv_B,
                         const float* __restrict__ W_proj,
                         const float* __restrict__ W_idk, const float* __restrict__ idk_A,
                         const float* __restrict__ idk_B) {
    int idx = blockIdx.x * 256 + threadIdx.x;
    if (idx < QKV_N) {
        int o = idx % (3 * CC), c = idx / (3 * CC);
        int g = o / CC, oc = o % CC;
        float s = 0.f;
        #pragma unroll
        for (int r = 0; r < 8; r++)
            s += qkv_B[(g * CC + oc) * 8 + r] * qkv_A[(g * 8 + r) * CC + c];
        g_WtQKV[c * (3 * CC) + o] = W_qkv[o * CC + c] + SCALE * s;
        return;
    }
    idx -= QKV_N;
    if (idx < IDV_N) {
        int o = idx % CC, c = idx / CC;
        float s = 0.f;
        #pragma unroll
        for (int r = 0; r < 8; r++)
            s += idv_B[o * 8 + r] * idv_A[r * CC + c];
        g_WtIDV[c * CC + o] = W_idv[o * CC + c] + SCALE * s;
        return;
    }
    idx -= IDV_N;
    if (idx < PROJ_N) {
        int o = idx % CC, c = idx / CC;
        g_WtPROJ[c * CC + o] = W_proj[o * CC + c];
        return;
    }
    idx -= PROJ_N;
    if (idx < IDK_N) {
        int h = idx / CC, c = idx % CC;
        float s = 0.f;
        #pragma unroll
        for (int r = 0; r < 8; r++)
            s += idk_B[h * 8 + r] * idk_A[r * CC + c];
        g_WIDK[idx] = W_idk[idx] + SCALE * s;
    }
}

// ---------------- generic SGEMM: C(M,N) = A(M,K) @ Bt(K,N) + bias ----------------
// 128x128 tile, BK=8, 256 threads, 8x8 per thread, float4 smem reads,
// register-prefetch + DOUBLE-BUFFERED smem: ONE barrier per k-step.
__global__ void __launch_bounds__(256) sgemm128(const float* __restrict__ A,
                                                const float* __restrict__ Bt,
                                                const float* __restrict__ bias,
                                                float* __restrict__ C,
                                                int M, int N, int K) {
    __shared__ float As[2][8][128];
    __shared__ float Bs[2][8][128];
    int tid = threadIdx.x;
    int bx = blockIdx.x * 128;   // N
    int by = blockIdx.y * 128;   // M
    int tR = tid / 16, tC = tid % 16;
    float acc[8][8];
    #pragma unroll
    for (int i = 0; i < 8; i++)
        #pragma unroll
        for (int j = 0; j < 8; j++) acc[i][j] = 0.f;

    int aRow = tid / 2, aCol = (tid % 2) * 4;
    int bRow = tid / 32, bCol = (tid % 32) * 4;
    const float* Aptr = A + (long)(by + aRow) * K + aCol;
    const float* Bptr = Bt + (long)bRow * N + bx + bCol;

    // prologue: load tile 0 and commit to buffer 0
    float4 a4 = *(const float4*)(Aptr);
    float4 b4 = *(const float4*)(Bptr);
    As[0][aCol + 0][aRow] = a4.x;
    As[0][aCol + 1][aRow] = a4.y;
    As[0][aCol + 2][aRow] = a4.z;
    As[0][aCol + 3][aRow] = a4.w;
    *(float4*)&Bs[0][bRow][bCol] = b4;
    __syncthreads();

    int buf = 0;
    for (int k0 = 0; k0 < K; k0 += 8, buf ^= 1) {
        bool has_next = (k0 + 8 < K);
        if (has_next) {
            a4 = *(const float4*)(Aptr + k0 + 8);
            b4 = *(const float4*)(Bptr + (long)(k0 + 8) * N);
        }
        #pragma unroll
        for (int k = 0; k < 8; k++) {
            float4 ra0 = *(const float4*)&As[buf][k][tR * 8];
            float4 ra1 = *(const float4*)&As[buf][k][tR * 8 + 4];
            float4 rb0 = *(const float4*)&Bs[buf][k][tC * 8];
            float4 rb1 = *(const float4*)&Bs[buf][k][tC * 8 + 4];
            float ra[8] = {ra0.x, ra0.y, ra0.z, ra0.w, ra1.x, ra1.y, ra1.z, ra1.w};
            float rb[8] = {rb0.x, rb0.y, rb0.z, rb0.w, rb1.x, rb1.y, rb1.z, rb1.w};
            #pragma unroll
            for (int i = 0; i < 8; i++)
                #pragma unroll
                for (int j = 0; j < 8; j++) acc[i][j] += ra[i] * rb[j];
        }
        if (has_next) {
            int nb = buf ^ 1;
            As[nb][aCol + 0][aRow] = a4.x;
            As[nb][aCol + 1][aRow] = a4.y;
            As[nb][aCol + 2][aRow] = a4.z;
            As[nb][aCol + 3][aRow] = a4.w;
            *(float4*)&Bs[nb][bRow][bCol] = b4;
            __syncthreads();
        }
    }
    #pragma unroll
    for (int i = 0; i < 8; i++) {
        int row = by + tR * 8 + i;
        #pragma unroll
        for (int j = 0; j < 8; j += 4) {
            int col = bx + tC * 8 + j;
            float4 o;
            o.x = acc[i][j + 0] + bias[col + 0];
            o.y = acc[i][j + 1] + bias[col + 1];
            o.z = acc[i][j + 2] + bias[col + 2];
            o.w = acc[i][j + 3] + bias[col + 3];
            *(float4*)(C + (long)row * N + col) = o;
        }
    }
}

// ---------------- ID_K: (1024 tokens, 12 heads) ----------------
__global__ void idk_kernel(const float* __restrict__ id_total, const float* __restrict__ b_idk) {
    int token = blockIdx.x;                 // 0..1023 (= b*256+n)
    int w = threadIdx.x >> 5, lane = threadIdx.x & 31;  // 12 warps
    const float* row = id_total + (long)token * CC;
    const float* wr = g_WIDK + w * CC;
    float s = 0.f;
    for (int c = lane; c < CC; c += 32) s += row[c] * wr[c];
    #pragma unroll
    for (int o = 16; o > 0; o >>= 1) s += __shfl_down_sync(0xffffffffu, s, o);
    if (lane == 0) g_IDK[token * HH + w] = s + b_idk[w];
}

// ---------------- k_m_id / v_m_id (also the 2nd & 3rd outputs) ----------------
__global__ void kvmid_kernel(float* __restrict__ kmid, float* __restrict__ vmid) {
    int idx = blockIdx.x * 256 + threadIdx.x;
    if (idx >= BB * HH * NM * DD) return;
    int d = idx & 63;
    int t = idx >> 6;
    int n = t & 255; t >>= 8;
    int h = t % HH;  int b = t / HH;
    const float* q = g_QKV + (long)(b * NN + n) * (3 * CC);
    float idk = g_IDK[(b * NM + n) * HH + h];
    kmid[idx] = q[CC + h * DD + d] * (1.0f + tanhf(idk));
    vmid[idx] = q[2 * CC + h * DD + d] + g_IDV[(long)(b * NM + n) * CC + h * DD + d];
}

// ---------------- fused attn over memory tokens (256 keys, top-128) ----------------
// grid (NM/8, H, B), 256 threads
__global__ void __launch_bounds__(256) attn_m_kernel(const float* __restrict__ kmid,
                                                     const float* __restrict__ vmid) {
    extern __shared__ float sm[];
    float* Qs = sm;                 // 512
    float* Ks = Qs + 512;           // 256*KST
    float* Vs = Ks + 256 * KST;     // 256*KST
    float* Sc = Vs + 256 * KST;     // 8*256
    float* red = Sc + 8 * 256;      // 256
    unsigned* hist = (unsigned*)(red + 256); // 256
    __shared__ unsigned s_pfx;
    __shared__ int s_remain;

    int tid = threadIdx.x;
    int q0 = blockIdx.x * 8, h = blockIdx.y, b = blockIdx.z;
    int bh = b * HH + h;

    for (int i = tid; i < 8 * DD; i += 256) {
        int qq = i >> 6, d = i & 63;
        Qs[i] = g_QKV[(long)(b * NN + q0 + qq) * (3 * CC) + h * DD + d] * QSC;
    }
    for (int i = tid; i < NM * DD; i += 256) {
        int kk = i >> 6, d = i & 63;
        Ks[kk * KST + d] = kmid[((long)bh * NM + kk) * DD + d];
        Vs[kk * KST + d] = vmid[((long)bh * NM + kk) * DD + d];
    }
    __syncthreads();

    {
        const float4* K4 = (const float4*)&Ks[tid * KST];
        for (int qq = 0; qq < 8; qq++) {
            const float4* Q4 = (const float4*)&Qs[qq * DD];
            float s = 0.f;
            #pragma unroll
            for (int d4 = 0; d4 < DD / 4; d4++) {
                float4 kv = K4[d4], qv = Q4[d4];
                s += qv.x * kv.x + qv.y * kv.y + qv.z * kv.z + qv.w * kv.w;
            }
            Sc[qq * 256 + tid] = s;
        }
    }
    __syncthreads();

    for (int qq = 0; qq < 8; qq++) {
        float* row = Sc + qq * 256;
        float myv = row[tid];
        float mx = block_reduce_max<256>(myv, red, tid);
        // radix select top-128 threshold
        if (tid == 0) { s_pfx = 0u; s_remain = TOPM; }
        __syncthreads();
        for (int pass = 0; pass < 4; pass++) {
            int shift = 24 - pass * 8;
            hist[tid] = 0u;
            __syncthreads();
            unsigned pmask = (pass == 0) ? 0u : (0xFFFFFFFFu << (shift + 8));
            unsigned pfx = s_pfx;
            unsigned u = f2u(myv);
            unsigned bin = ((u & pmask) == pfx) ? ((u >> shift) & 255u) : 0xffffffffu;
            hist_add_warp(hist, bin);
            __syncthreads();
            hist_select_warp(hist, tid, pfx, shift, &s_pfx, &s_remain);
            __syncthreads();
        }
        unsigned thr = s_pfx;
        float w = (f2u(myv) >= thr) ? __expf(myv - mx) : 0.f;
        row[tid] = w;
        float sum = block_reduce_sum<256>(w, red, tid);
        float inv = 1.0f / sum;
        // AV
        int g = tid >> 6, d = tid & 63;
        float acc = 0.f;
        for (int i = g; i < NM; i += 4) acc += row[i] * Vs[i * KST + d];
        red[tid] = acc; __syncthreads();
        if (tid < 64) {
            float o = (red[tid] + red[tid + 64] + red[tid + 128] + red[tid + 192]) * inv;
            g_XO[(long)(b * NN + q0 + qq) * CC + h * DD + tid] = o;
        }
        __syncthreads();
    }
}

// ---------------- fused attn over full keys (2560 keys, top-640) ----------------
// grid (NS/QT, H, B), NT=512 threads, QT=16 queries per block
__global__ void __launch_bounds__(NT) attn_s_kernel(const float* __restrict__ mem_k,
                                                    const float* __restrict__ mem_v,
                                                    const float* __restrict__ vmid) {
    extern __shared__ float sm[];
    float* Qs = sm;                   // QT*64 = 1024
    float* Ks = Qs + QT * DD;         // 64*KST = 4352
    float* Sc = Ks + 64 * KST;        // QT*2560 = 40960
    float* red = Sc + QT * KFULL;     // NT = 512
    float* selw = red + NT;           // 704
    int*   selidx = (int*)(selw + 704);       // 704
    unsigned* hist = (unsigned*)(selidx + 704); // 256
    __shared__ unsigned s_pfx;
    __shared__ int s_remain;
    __shared__ int s_cnt;

    int tid = threadIdx.x;
    int q0 = blockIdx.x * QT, h = blockIdx.y, b = blockIdx.z;
    int bh = b * HH + h;

    for (int i = tid; i < QT * DD; i += NT) {
        int qq = i >> 6, d = i & 63;
        Qs[i] = g_QKV[(long)(b * NN + NM + q0 + qq) * (3 * CC) + h * DD + d] * QSC;
    }
    __syncthreads();

    // scores in 64-key chunks
    for (int c0 = 0; c0 < KFULL; c0 += 64) {
        for (int i = tid; i < 64 * DD; i += NT) {
            int kl = i >> 6, d = i & 63;
            int kg = c0 + kl;
            float v;
            if (kg < MEM)
                v = mem_k[((long)bh * MEM + kg) * DD + d];
            else
                v = g_QKV[(long)(b * NN + (kg - MEM)) * (3 * CC) + CC + h * DD + d];
            Ks[kl * KST + d] = v;
        }
        __syncthreads();
        int kl = tid & 63, qp = tid >> 6;   // 8 q-groups
        const float4* K4 = (const float4*)&Ks[kl * KST];
        #pragma unroll
        for (int qi = 0; qi < QT / 8; qi++) {
            int qq = qp + qi * 8;
            const float4* Q4 = (const float4*)&Qs[qq * DD];
            float s = 0.f;
            #pragma unroll
            for (int d4 = 0; d4 < DD / 4; d4++) {
                float4 kv = K4[d4], qv = Q4[d4];
                s += qv.x * kv.x + qv.y * kv.y + qv.z * kv.z + qv.w * kv.w;
            }
            Sc[qq * KFULL + c0 + kl] = s;
        }
        __syncthreads();
    }

    for (int qq = 0; qq < QT; qq++) {
        float* row = Sc + qq * KFULL;
        // row max
        float mv = -1e30f;
        for (int i = tid; i < KFULL; i += NT) mv = fmaxf(mv, row[i]);
        float mx = block_reduce_max<NT>(mv, red, tid);
        // radix select top-640 threshold
        if (tid == 0) { s_pfx = 0u; s_remain = TOPS; s_cnt = 0; }
        __syncthreads();
        for (int pass = 0; pass < 4; pass++) {
            int shift = 24 - pass * 8;
            if (tid < 256) hist[tid] = 0u;
            __syncthreads();
            unsigned pmask = (pass == 0) ? 0u : (0xFFFFFFFFu << (shift + 8));
            unsigned pfx = s_pfx;
            for (int i = tid; i < KFULL; i += NT) {
                unsigned u = f2u(row[i]);
                unsigned bin = ((u & pmask) == pfx) ? ((u >> shift) & 255u) : 0xffffffffu;
                hist_add_warp(hist, bin);
            }
            __syncthreads();
            hist_select_warp(hist, tid, pfx, shift, &s_pfx, &s_remain);
            __syncthreads();
        }
        unsigned thr = s_pfx;
        // compact selected + weight sum (warp-aggregated s_cnt)
        float lsum = 0.f;
        int lane = tid & 31;
        for (int i = tid; i < KFULL; i += NT) {
            float v = row[i];
            bool sel = (f2u(v) >= thr);
            unsigned ballot = __ballot_sync(0xffffffffu, sel);
            int base = 0;
            if (ballot) {
                int leader = __ffs(ballot) - 1;
                if (lane == leader) base = atomicAdd(&s_cnt, __popc(ballot));
                base = __shfl_sync(0xffffffffu, base, leader);
            }
            if (sel) {
                float w = __expf(v - mx);
                int p = base + __popc(ballot & ((1u << lane) - 1u));
                if (p < 704) { selidx[p] = i; selw[p] = w; }
                lsum += w;
            }
        }
        float sum = block_reduce_sum<NT>(lsum, red, tid);
        float inv = 1.0f / sum;
        int cnt = min(s_cnt, 704);
        __syncthreads();
        // AV over compacted selection (8-way key parallelism, 4x unrolled gather
        // so 4 independent LDGs are in flight -> MLP>=4 hides L2 latency)
        int g = tid >> 6, d = tid & 63;
        float acc = 0.f;
        const float* vm = mem_v + (long)bh * MEM * DD;
        const float* vs = vmid + (long)bh * NM * DD;
        const float* vq = g_QKV + (long)b * NN * (3 * CC) + 2 * CC + h * DD;
        int j = g;
        for (; j + 24 < cnt; j += 32) {
            int i0 = selidx[j], i1 = selidx[j + 8], i2 = selidx[j + 16], i3 = selidx[j + 24];
            float w0 = selw[j], w1 = selw[j + 8], w2 = selw[j + 16], w3 = selw[j + 24];
            const float* p0 = (i0 < MEM) ? vm + (long)i0 * DD
                             : (i0 < MEM + NM) ? vs + (long)(i0 - MEM) * DD
                             : vq + (long)(i0 - MEM) * (3 * CC);
            const float* p1 = (i1 < MEM) ? vm + (long)i1 * DD
                             : (i1 < MEM + NM) ? vs + (long)(i1 - MEM) * DD
                             : vq + (long)(i1 - MEM) * (3 * CC);
            const float* p2 = (i2 < MEM) ? vm + (long)i2 * DD
                             : (i2 < MEM + NM) ? vs + (long)(i2 - MEM) * DD
                             : vq + (long)(i2 - MEM) * (3 * CC);
            const float* p3 = (i3 < MEM) ? vm + (long)i3 * DD
                             : (i3 < MEM + NM) ? vs + (long)(i3 - MEM) * DD
                             : vq + (long)(i3 - MEM) * (3 * CC);
            float v0 = p0[d], v1 = p1[d], v2 = p2[d], v3 = p3[d];
            acc += w0 * v0 + w1 * v1 + w2 * v2 + w3 * v3;
        }
        for (; j < cnt; j += 8) {
            int idx = selidx[j];
            const float* vrow = (idx < MEM) ? vm + (long)idx * DD
                               : (idx < MEM + NM) ? vs + (long)(idx - MEM) * DD
                               : vq + (long)(idx - MEM) * (3 * CC);
            acc += selw[j] * vrow[d];
        }
        red[tid] = acc; __syncthreads();
        if (tid < 64) {
            float o = 0.f;
            #pragma unroll
            for (int k2 = 0; k2 < 8; k2++) o += red[tid + k2 * 64];
            g_XO[(long)(b * NN + NM + q0 + qq) * CC + h * DD + tid] = o * inv;
        }
        __syncthreads();
    }
}

// ---------------- MoE routed LoRA add: out += scale * sum_e route_e * B_e @ (A_e @ xo) ----------------
__global__ void moe_kernel(const float* __restrict__ route_W, const float* __restrict__ proj_A,
                           const float* __restrict__ proj_B, float* __restrict__ out) {
    __shared__ float row[CC];
    __shared__ float dots[36];
    __shared__ float coef[32];
    int token = blockIdx.x, tid = threadIdx.x;
    for (int i = tid; i < CC; i += 256) row[i] = g_XO[(long)token * CC + i];
    __syncthreads();
    int w = tid >> 5, lane = tid & 31;
    for (int j = w; j < 36; j += 8) {
        const float* vec = (j < 4) ? (route_W + (long)j * CC) : (proj_A + (long)(j - 4) * CC);
        float s = 0.f;
        for (int c = lane; c < CC; c += 32) s += row[c] * vec[c];
        #pragma unroll
        for (int o = 16; o > 0; o >>= 1) s += __shfl_down_sync(0xffffffffu, s, o);
        if (lane == 0) dots[j] = s;
    }
    __syncthreads();
    if (tid == 0) {
        float m = fmaxf(fmaxf(dots[0], dots[1]), fmaxf(dots[2], dots[3]));
        float e0 = __expf(dots[0] - m), e1 = __expf(dots[1] - m);
        float e2 = __expf(dots[2] - m), e3 = __expf(dots[3] - m);
        float inv = 1.f / (e0 + e1 + e2 + e3);
        float p[4] = {e0 * inv, e1 * inv, e2 * inv, e3 * inv};
        for (int e = 0; e < 4; e++)
            for (int r = 0; r < 8; r++)
                coef[e * 8 + r] = p[e] * dots[4 + e * 8 + r] * SCALE;
    }
    __syncthreads();
    for (int c = tid; c < CC; c += 256) {
        float acc = 0.f;
        #pragma unroll
        for (int e = 0; e < 4; e++)
            #pragma unroll
            for (int r = 0; r < 8; r++)
                acc += coef[e * 8 + r] * proj_B[((long)e * CC + c) * 8 + r];
        out[(long)token * CC + c] += acc;
    }
}

// ---------------- host ----------------
extern "C" void kernel_launch(void* const* d_in, const int* in_sizes, int n_in,
                              void* d_out, int out_size) {
    const float* x        = (const float*)d_in[0];
    const float* id_total = (const float*)d_in[1];
    const float* mem_k    = (const float*)d_in[2];
    const float* mem_v    = (const float*)d_in[3];
    const float* W_qkv    = (const float*)d_in[4];
    const float* b_qkv    = (const float*)d_in[5];
    const float* qkv_A    = (const float*)d_in[6];
    const float* qkv_B    = (const float*)d_in[7];
    const float* W_proj   = (const float*)d_in[8];
    const float* b_proj   = (const float*)d_in[9];
    const float* route_W  = (const float*)d_in[10];
    const float* proj_A   = (const float*)d_in[11];
    const float* proj_B   = (const float*)d_in[12];
    const float* W_idk    = (const float*)d_in[13];
    const float* b_idk    = (const float*)d_in[14];
    const float* idk_A    = (const float*)d_in[15];
    const float* idk_B    = (const float*)d_in[16];
    const float* W_idv    = (const float*)d_in[17];
    const float* b_idv    = (const float*)d_in[18];
    const float* idv_A    = (const float*)d_in[19];
    const float* idv_B    = (const float*)d_in[20];

    float* out  = (float*)d_out;                      // (4,1280,768)
    float* kmid = out + (long)BB * NN * CC;           // (4,12,256,64)
    float* vmid = kmid + (long)BB * HH * NM * DD;     // (4,12,256,64)

    void *p_WtQKV, *p_WtIDV, *p_WtPROJ, *p_QKV, *p_IDV, *p_XO;
    cudaGetSymbolAddress(&p_WtQKV, g_WtQKV);
    cudaGetSymbolAddress(&p_WtIDV, g_WtIDV);
    cudaGetSymbolAddress(&p_WtPROJ, g_WtPROJ);
    cudaGetSymbolAddress(&p_QKV, g_QKV);
    cudaGetSymbolAddress(&p_IDV, g_IDV);
    cudaGetSymbolAddress(&p_XO, g_XO);

    // 1: prep (fold LoRA, transpose weights) — single kernel
    prep_all<<<(PREP_TOTAL + 255) / 256, 256>>>(W_qkv, qkv_A, qkv_B,
                                                W_idv, idv_A, idv_B,
                                                W_proj,
                                                W_idk, idk_A, idk_B);

    // 2: QKV gemm: (5120,768) @ (768,2304)
    {
        dim3 grid(3 * CC / 128, BB * NN / 128);
        sgemm128<<<grid, 256>>>(x, (const float*)p_WtQKV, b_qkv, (float*)p_QKV,
                                BB * NN, 3 * CC, CC);
    }
    // 3: ID_K
    idk_kernel<<<BB * NM, HH * 32>>>(id_total, b_idk);
    // 4: ID_V gemm: (1024,768) @ (768,768)
    {
        dim3 grid(CC / 128, BB * NM / 128);
        sgemm128<<<grid, 256>>>(id_total, (const float*)p_WtIDV, b_idv, (float*)p_IDV,
                                BB * NM, CC, CC);
    }
    // 5: k_m_id / v_m_id -> outputs 2 & 3
    kvmid_kernel<<<(BB * HH * NM * DD + 255) / 256, 256>>>(kmid, vmid);

    // 6: attention over full keys (hot — placed here for ncu capture)
    {
        size_t smem = (size_t)(QT * DD + 64 * KST + QT * KFULL + NT + 704 + 704 + 256) * 4;
        cudaFuncSetAttribute(attn_s_kernel, cudaFuncAttributeMaxDynamicSharedMemorySize, (int)smem);
        dim3 grid(NS / QT, HH, BB);
        attn_s_kernel<<<grid, NT, smem>>>(mem_k, mem_v, vmid);
    }
    // 7: attention over memory tokens
    {
        size_t smem = (size_t)(512 + 256 * KST + 256 * KST + 8 * 256 + 256 + 256) * 4;
        cudaFuncSetAttribute(attn_m_kernel, cudaFuncAttributeMaxDynamicSharedMemorySize, (int)smem);
        dim3 grid(NM / 8, HH, BB);
        attn_m_kernel<<<grid, 256, smem>>>(kmid, vmid);
    }
    // 8: output projection gemm: (5120,768) @ (768,768) -> out
    {
        dim3 grid(CC / 128, BB * NN / 128);
        sgemm128<<<grid, 256>>>((const float*)p_XO, (const float*)p_WtPROJ, b_proj, out,
                                BB * NN, CC, CC);
    }
    // 9: MoE routed LoRA add
    moe_kernel<<<BB * NN, 256>>>(route_W, proj_A, proj_B, out);

    (void)in_sizes; (void)n_in; (void)out_size;
}